// round 6
// baseline (speedup 1.0000x reference)
#include <cuda_runtime.h>
#include <cuda_bf16.h>
#include <cstdint>

// Arch-feature gate: tcgen05 only exists in sm_103a-family passes. In the
// compute_103 (PTX) pass this is 0 and we compile an mma.sync fallback.
#if defined(__CUDA_ARCH__) && defined(__CUDA_ARCH_HAS_FEATURE__)
#if __CUDA_ARCH_HAS_FEATURE__(SM103_ALL)
#define HAS_TC 1
#else
#define HAS_TC 0
#endif
#else
#define HAS_TC 0
#endif

// ---------------- problem dims (fixed by setup_inputs) ----------------
namespace cfg {
constexpr int M = 8192;     // B*S
constexpr int N = 4096;     // D_OUT
constexpr int K = 4096;     // D_IN
constexpr int BM = 256, BN = 256, BK = 64;
constexpr int STAGES = 3;
constexpr int NK = K / BK;                       // 64
constexpr int A_STAGE = BM * BK * 2;             // 32768
constexpr int B_STAGE = BN * BK * 2;             // 32768
constexpr int SMEM_A_OFF = 1024;
constexpr int SMEM_B_OFF = SMEM_A_OFF + STAGES * A_STAGE;   // 99328
constexpr int SMEM_TOTAL = SMEM_B_OFF + STAGES * B_STAGE;   // 197632
constexpr int MBAR_OFF = 64;
// tcgen05 idesc per-MMA is M=128 x N=256: dtype F32(bit4), atype BF16(bit7),
// btype BF16(bit10), N/8<<17, M/16<<24
constexpr uint32_t IDESC = 0x10u | 0x80u | 0x400u | ((256 / 8) << 17) | ((128 / 16) << 24);
}

// ---------------- scratch ----------------
__device__ __nv_bfloat16 g_X [(size_t)cfg::M * cfg::K];   // x in bf16, [M][K]
__device__ __nv_bfloat16 g_Wt[(size_t)cfg::N * cfg::K];   // W^T bf16, [N][K] K-major
__device__ float         g_H [cfg::M * 8];                // LoRA hidden
__device__ int           g_q_is_int32;

__constant__ float c_nf4[16] = {
    -1.0f, -0.6962f, -0.5251f, -0.3949f, -0.2844f, -0.1848f, -0.0911f, 0.0f,
     0.0796f, 0.1609f, 0.2461f, 0.3379f, 0.4407f, 0.5626f, 0.723f, 1.0f};

// ---------------- generic helpers ----------------
__device__ __forceinline__ uint32_t smem_u32(const void* p) {
    return (uint32_t)__cvta_generic_to_shared(p);
}
__device__ __forceinline__ void cp_async16(uint32_t s, const void* g) {
    asm volatile("cp.async.cg.shared.global [%0], [%1], 16;" :: "r"(s), "l"(g));
}
__device__ __forceinline__ void cp_commit() { asm volatile("cp.async.commit_group;"); }
template <int W>
__device__ __forceinline__ void cp_wait() {
    asm volatile("cp.async.wait_group %0;" :: "n"(W));
}
__device__ __forceinline__ uint32_t sw128(uint32_t b) { return b ^ ((b >> 3) & 0x70); }

__device__ __forceinline__ void ldsm_x4(uint32_t a[4], uint32_t addr) {
    asm volatile("ldmatrix.sync.aligned.m8n8.x4.shared.b16 {%0,%1,%2,%3}, [%4];"
                 : "=r"(a[0]), "=r"(a[1]), "=r"(a[2]), "=r"(a[3]) : "r"(addr));
}
__device__ __forceinline__ void mma16816(float d[4], const uint32_t a[4],
                                         uint32_t b0, uint32_t b1) {
    asm volatile(
        "mma.sync.aligned.m16n8k16.row.col.f32.bf16.bf16.f32 "
        "{%0,%1,%2,%3}, {%4,%5,%6,%7}, {%8,%9}, {%0,%1,%2,%3};"
        : "+f"(d[0]), "+f"(d[1]), "+f"(d[2]), "+f"(d[3])
        : "r"(a[0]), "r"(a[1]), "r"(a[2]), "r"(a[3]), "r"(b0), "r"(b1));
}

#if HAS_TC
// ---------------- tcgen05-only helpers (sm_103a pass only) ----------------
__device__ __forceinline__ uint32_t elect_one() {
    uint32_t pred;
    asm volatile("{\n\t.reg .pred p;\n\telect.sync _|p, 0xFFFFFFFF;\n\t"
                 "selp.b32 %0, 1, 0, p;\n\t}" : "=r"(pred));
    return pred;
}
__device__ __forceinline__ uint64_t make_desc(uint32_t addr) {
    constexpr uint64_t BASE =
        (uint64_t(2) << 61) | (uint64_t(1) << 46) | (uint64_t(64) << 32) | (uint64_t(1) << 16);
    return BASE | ((uint64_t)(addr >> 4) & 0x3FFF);
}
__device__ __forceinline__ void mma_f16_ss(uint32_t d, uint64_t a, uint64_t b,
                                           uint32_t idesc, uint32_t en) {
    asm volatile(
        "{\n\t.reg .pred p;\n\tsetp.ne.u32 p, %5, 0;\n\t"
        "tcgen05.mma.cta_group::1.kind::f16 [%0], %1, %2, %3, {%4, %4, %4, %4}, p;\n\t}"
        :: "r"(d), "l"(a), "l"(b), "r"(idesc), "r"(0u), "r"(en) : "memory");
}
__device__ __forceinline__ void tc_commit(uint32_t mbar) {
    asm volatile(
        "tcgen05.commit.cta_group::1.mbarrier::arrive::one.shared::cluster.b64 [%0];"
        :: "r"(mbar) : "memory");
}
__device__ __forceinline__ void mbar_init(uint32_t mbar, uint32_t cnt) {
    asm volatile("mbarrier.init.shared.b64 [%0], %1;" :: "r"(mbar), "r"(cnt) : "memory");
}
__device__ __forceinline__ void mbar_wait(uint32_t mbar, uint32_t parity) {
    uint32_t done;
    asm volatile(
        "{\n\t.reg .pred p;\n\t"
        "mbarrier.try_wait.parity.acquire.cta.shared::cta.b64 p, [%1], %2;\n\t"
        "selp.b32 %0, 1, 0, p;\n\t}"
        : "=r"(done) : "r"(mbar), "r"(parity) : "memory");
    if (!done) {
        asm volatile(
            "{\n\t.reg .pred P1;\n\t"
            "WAIT_LOOP_%=:\n\t"
            "mbarrier.try_wait.parity.acquire.cta.shared::cta.b64 P1, [%0], %1, 0x989680;\n\t"
            "@P1 bra.uni WAIT_DONE_%=;\n\t"
            "bra.uni WAIT_LOOP_%=;\n\t"
            "WAIT_DONE_%=:\n\t}"
            :: "r"(mbar), "r"(parity) : "memory");
    }
}
__device__ __forceinline__ void fence_proxy_async_cta() {
    asm volatile("fence.proxy.async.shared::cta;" ::: "memory");
}
__device__ __forceinline__ void tc_fence_after() {
    asm volatile("tcgen05.fence::after_thread_sync;" ::: "memory");
}
__device__ __forceinline__ void tc_fence_before() {
    asm volatile("tcgen05.fence::before_thread_sync;" ::: "memory");
}
__device__ __forceinline__ void tc_wait_ld() {
    asm volatile("tcgen05.wait::ld.sync.aligned;" ::: "memory");
}
__device__ __forceinline__ void ldtm_x32(uint32_t* r, uint32_t tmem_addr) {
    asm volatile(
        "tcgen05.ld.sync.aligned.32x32b.x32.b32 "
        "{%0, %1, %2, %3, %4, %5, %6, %7, "
        " %8, %9, %10, %11, %12, %13, %14, %15, "
        " %16, %17, %18, %19, %20, %21, %22, %23, "
        " %24, %25, %26, %27, %28, %29, %30, %31}, [%32];"
        : "=r"(r[0]),  "=r"(r[1]),  "=r"(r[2]),  "=r"(r[3]),
          "=r"(r[4]),  "=r"(r[5]),  "=r"(r[6]),  "=r"(r[7]),
          "=r"(r[8]),  "=r"(r[9]),  "=r"(r[10]), "=r"(r[11]),
          "=r"(r[12]), "=r"(r[13]), "=r"(r[14]), "=r"(r[15]),
          "=r"(r[16]), "=r"(r[17]), "=r"(r[18]), "=r"(r[19]),
          "=r"(r[20]), "=r"(r[21]), "=r"(r[22]), "=r"(r[23]),
          "=r"(r[24]), "=r"(r[25]), "=r"(r[26]), "=r"(r[27]),
          "=r"(r[28]), "=r"(r[29]), "=r"(r[30]), "=r"(r[31])
        : "r"(tmem_addr));
}
#endif  // HAS_TC

// ---------------- 0) detect qweight encoding ----------------
__global__ void k_detect(const unsigned* __restrict__ q) {
    __shared__ int ok;
    if (threadIdx.x == 0) ok = 1;
    __syncthreads();
    unsigned u = q[threadIdx.x];
    if ((unsigned)(u + 8u) >= 16u) atomicAnd(&ok, 0);
    __syncthreads();
    if (threadIdx.x == 0) g_q_is_int32 = ok;
}

// ---------------- 1) fused: LoRA hidden H = x @ lora_a  AND  x -> bf16 -------
__global__ void __launch_bounds__(128) k_lora_conv(
    const float* __restrict__ x, const float* __restrict__ la) {
    using namespace cfg;
    const int warp = threadIdx.x >> 5, lane = threadIdx.x & 31;
    const int m0 = blockIdx.x * 32 + warp * 8;
    float acc[8][8];
#pragma unroll
    for (int i = 0; i < 8; i++)
#pragma unroll
        for (int j = 0; j < 8; j++) acc[i][j] = 0.0f;

    for (int it = 0; it < K / 64; it++) {
        const int k = it * 64 + lane * 2;
        float4 a0 = *reinterpret_cast<const float4*>(la + (size_t)k * 8);
        float4 a1 = *reinterpret_cast<const float4*>(la + (size_t)k * 8 + 4);
        float4 a2 = *reinterpret_cast<const float4*>(la + (size_t)(k + 1) * 8);
        float4 a3 = *reinterpret_cast<const float4*>(la + (size_t)(k + 1) * 8 + 4);
#pragma unroll
        for (int rr = 0; rr < 8; rr++) {
            const size_t off = (size_t)(m0 + rr) * K + k;
            float2 xv = *reinterpret_cast<const float2*>(x + off);
            *reinterpret_cast<__nv_bfloat162*>(g_X + off) =
                __floats2bfloat162_rn(xv.x, xv.y);
            acc[rr][0] += xv.x * a0.x + xv.y * a2.x;
            acc[rr][1] += xv.x * a0.y + xv.y * a2.y;
            acc[rr][2] += xv.x * a0.z + xv.y * a2.z;
            acc[rr][3] += xv.x * a0.w + xv.y * a2.w;
            acc[rr][4] += xv.x * a1.x + xv.y * a3.x;
            acc[rr][5] += xv.x * a1.y + xv.y * a3.y;
            acc[rr][6] += xv.x * a1.z + xv.y * a3.z;
            acc[rr][7] += xv.x * a1.w + xv.y * a3.w;
        }
    }
#pragma unroll
    for (int rr = 0; rr < 8; rr++)
#pragma unroll
        for (int r = 0; r < 8; r++) {
            float v = acc[rr][r];
#pragma unroll
            for (int off = 16; off; off >>= 1)
                v += __shfl_xor_sync(0xffffffffu, v, off);
            if (lane == 0) g_H[(m0 + rr) * 8 + r] = v;
        }
}

// ---------------- 2) NF4 dequant + transpose: g_Wt[n][k] ----------------
__global__ void __launch_bounds__(256) k_dequant_t(
    const int* __restrict__ q, const float* __restrict__ scale) {
    using namespace cfg;
    __shared__ __nv_bfloat16 t[64][72];
    const int k0 = blockIdx.y * 64;
    const int n0 = blockIdx.x * 64;
    const int tid = threadIdx.x;
    const bool is32 = (g_q_is_int32 != 0);

    for (int idx = tid; idx < 64 * 64; idx += 256) {
        int kk = idx >> 6, nn = idx & 63;
        int code;
        if (is32) {
            code = q[(size_t)(k0 + kk) * N + n0 + nn] + 8;
        } else {
            code = (int)((const signed char*)q)[(size_t)(k0 + kk) * N + n0 + nn] + 8;
        }
        float s = scale[(size_t)((k0 + kk) >> 7) * N + n0 + nn];
        t[kk][nn] = __hmul(__float2bfloat16(c_nf4[code]), __float2bfloat16(s));
    }
    __syncthreads();
    for (int idx = tid; idx < 64 * 32; idx += 256) {
        int nn = idx >> 5, kp = idx & 31;
        __nv_bfloat162 v = __halves2bfloat162(t[2 * kp][nn], t[2 * kp + 1][nn]);
        *reinterpret_cast<__nv_bfloat162*>(g_Wt + (size_t)(n0 + nn) * K + k0 + 2 * kp) = v;
    }
}

// ---------------- 3) main GEMM (dual path) ----------------
// BM=256 x BN=256 x BK=64, 3-stage cp.async, SW128 128B-row K-major tiles.
// tcgen05 path: two cg1 MMAs per stage (D0 cols 0-255 = rows 0-127,
// D1 cols 256-511 = rows 128-255).
__global__ void __launch_bounds__(256, 1) k_gemm(
    const float* __restrict__ bias,
    const float* __restrict__ lb,      // lora_b [8][N]
    float* __restrict__ out) {
    using namespace cfg;
    extern __shared__ __align__(1024) char smem[];
    const uint32_t sbase = smem_u32(smem);
    const int tid  = threadIdx.x;
    const int warp = tid >> 5, lane = tid & 31;
    const int bm0 = blockIdx.y * BM;
    const int bn0 = blockIdx.x * BN;

    // Per-thread loop-invariant chunk offsets. A and B stage tiles are both
    // 256 rows x 128B, so one table serves both. 8 chunks of 16B per thread.
    uint32_t swoff[8], goff[8];
#pragma unroll
    for (int i = 0; i < 8; i++) {
        int c = tid + i * 256;
        int row = c >> 3, col = c & 7;
        swoff[i] = sw128(row * 128 + col * 16);
        goff[i]  = (uint32_t)row * (K * 2) + col * 16;
    }

#if HAS_TC
    // ================= tcgen05 path =================
    auto issue_loads = [&](int kt, int st) {
        const char* gA = reinterpret_cast<const char*>(g_X)
            + (size_t)bm0 * (K * 2) + (size_t)kt * (BK * 2);
        const char* gB = reinterpret_cast<const char*>(g_Wt)
            + (size_t)bn0 * (K * 2) + (size_t)kt * (BK * 2);
        uint32_t sA = sbase + SMEM_A_OFF + st * A_STAGE;
        uint32_t sB = sbase + SMEM_B_OFF + st * B_STAGE;
#pragma unroll
        for (int i = 0; i < 8; i++) cp_async16(sA + swoff[i], gA + goff[i]);
#pragma unroll
        for (int i = 0; i < 8; i++) cp_async16(sB + swoff[i], gB + goff[i]);
    };

    if (warp == 0) {
        asm volatile("tcgen05.alloc.cta_group::1.sync.aligned.shared::cta.b32 [%0], %1;"
                     :: "r"(sbase), "r"(512u) : "memory");
    }
    if (tid == 0) {
#pragma unroll
        for (int s = 0; s < STAGES; s++) mbar_init(sbase + MBAR_OFF + s * 8, 1);
    }
    __syncthreads();
    uint32_t tmem_base;
    asm volatile("ld.shared.b32 %0, [%1];" : "=r"(tmem_base) : "r"(sbase));

    issue_loads(0, 0); cp_commit();
    issue_loads(1, 1); cp_commit();

    for (int kt = 0; kt < NK; kt++) {
        const int st = kt % 3;
        cp_wait<1>();
        fence_proxy_async_cta();
        __syncthreads();

        if (tid < 32 && elect_one()) {
            uint32_t aoff = sbase + SMEM_A_OFF + st * A_STAGE;
            uint64_t ad0 = make_desc(aoff);
            uint64_t ad1 = make_desc(aoff + 128 * 128);   // rows 128-255
            uint64_t bd  = make_desc(sbase + SMEM_B_OFF + st * B_STAGE);
            uint32_t en = (kt > 0) ? 1u : 0u;
#pragma unroll
            for (int ks = 0; ks < 4; ks++) {
                mma_f16_ss(tmem_base,        ad0 + ks * 2, bd + ks * 2, IDESC,
                           en | (ks > 0 ? 1u : 0u));
                mma_f16_ss(tmem_base + 256u, ad1 + ks * 2, bd + ks * 2, IDESC,
                           en | (ks > 0 ? 1u : 0u));
            }
            tc_commit(sbase + MBAR_OFF + st * 8);
        }

        const int kn = kt + 2;
        if (kn < NK) {
            const int sn = kn % 3;
            const int u  = kn / 3;
            if (u >= 1) mbar_wait(sbase + MBAR_OFF + sn * 8, (u - 1) & 1);
            issue_loads(kn, sn);
        }
        cp_commit();
    }

    // last commit: kt=63 -> stage 0, use index 21 -> parity 1
    mbar_wait(sbase + MBAR_OFF + 0 * 8, 1);
    tc_fence_after();

    // epilogue: LDTM -> bf16 round + bias + LoRA delta -> smem transpose -> store
    {
        const int mh = warp >> 2;          // M half (D0 / D1)
        const int rg = warp & 3;           // TMEM subpartition
        const int m = bm0 + mh * 128 + rg * 32 + lane;
        float4 ha = *reinterpret_cast<const float4*>(g_H + m * 8);
        float4 hb = *reinterpret_cast<const float4*>(g_H + m * 8 + 4);
        float h[8] = {ha.x, ha.y, ha.z, ha.w, hb.x, hb.y, hb.z, hb.w};
        float* sc = reinterpret_cast<float*>(smem + 1024) + warp * (32 * 33);
        const uint32_t dbase = tmem_base + (uint32_t)mh * 256u;

#pragma unroll
        for (int chunk = 0; chunk < 8; chunk++) {
            const int c0 = chunk * 32;
            uint32_t d[32];
            ldtm_x32(d, dbase + c0);
            tc_wait_ld();
            const int n_base = bn0 + c0;
#pragma unroll
            for (int r = 0; r < 32; r++) {
                const int n = n_base + r;
                float delta = 0.0f;
#pragma unroll
                for (int rr = 0; rr < 8; rr++) delta += h[rr] * lb[rr * N + n];
                __nv_bfloat16 bsum = __hadd(__float2bfloat16(__uint_as_float(d[r])),
                                            __float2bfloat16(bias[n]));
                sc[lane * 33 + r] = __bfloat162float(bsum) + 2.0f * delta;
            }
            __syncwarp();
#pragma unroll
            for (int r = 0; r < 32; r++) {
                out[(size_t)(bm0 + mh * 128 + rg * 32 + r) * N + n_base + lane] =
                    sc[r * 33 + lane];
            }
            __syncwarp();
        }
    }
    tc_fence_before();
    __syncthreads();
    if (warp == 0) {
        asm volatile("tcgen05.dealloc.cta_group::1.sync.aligned.b32 %0, %1;"
                     :: "r"(tmem_base), "r"(512u));
    }

#else
    // ================= mma.sync fallback (compute_103 PTX pass only) =======
    // Two passes over M halves, warp tile 64x64, 3-stage pipeline.
    const int wm = warp >> 2;          // 0..1 (within the 128-row half)
    const int wn = warp & 3;           // 0..3

    for (int mh = 0; mh < 2; mh++) {
        auto fb_loads = [&](int kt, int st) {
            const char* gA = reinterpret_cast<const char*>(g_X)
                + (size_t)(bm0 + mh * 128) * (K * 2) + (size_t)kt * (BK * 2);
            const char* gB = reinterpret_cast<const char*>(g_Wt)
                + (size_t)bn0 * (K * 2) + (size_t)kt * (BK * 2);
            uint32_t sA = sbase + SMEM_A_OFF + st * A_STAGE;
            uint32_t sB = sbase + SMEM_B_OFF + st * B_STAGE;
#pragma unroll
            for (int i = 0; i < 4; i++) cp_async16(sA + swoff[i], gA + goff[i]);
#pragma unroll
            for (int i = 0; i < 8; i++) cp_async16(sB + swoff[i], gB + goff[i]);
        };

        float acc[4][8][4];
#pragma unroll
        for (int i = 0; i < 4; i++)
#pragma unroll
            for (int j = 0; j < 8; j++)
#pragma unroll
                for (int e = 0; e < 4; e++) acc[i][j][e] = 0.0f;

        fb_loads(0, 0); cp_commit();
        fb_loads(1, 1); cp_commit();

        for (int kt = 0; kt < NK; kt++) {
            const int st = kt % 3;
            cp_wait<1>();
            __syncthreads();
            const int kn = kt + 2;
            if (kn < NK) fb_loads(kn, kn % 3);
            cp_commit();

            const uint32_t aST = sbase + SMEM_A_OFF + st * A_STAGE;
            const uint32_t bST = sbase + SMEM_B_OFF + st * B_STAGE;
#pragma unroll
            for (int ks = 0; ks < 4; ks++) {
                uint32_t afrag[4][4], bfrag[4][4];
#pragma unroll
                for (int mt = 0; mt < 4; mt++) {
                    int row = wm * 64 + mt * 16 + (lane & 15);
                    ldsm_x4(afrag[mt], aST + sw128(row * 128 + ks * 32 + (lane >> 4) * 16));
                }
#pragma unroll
                for (int nt = 0; nt < 4; nt++) {
                    int row = wn * 64 + nt * 16 + (lane & 15);
                    ldsm_x4(bfrag[nt], bST + sw128(row * 128 + ks * 32 + (lane >> 4) * 16));
                }
#pragma unroll
                for (int mt = 0; mt < 4; mt++)
#pragma unroll
                    for (int nt = 0; nt < 4; nt++) {
                        mma16816(acc[mt][2 * nt],     afrag[mt], bfrag[nt][0], bfrag[nt][2]);
                        mma16816(acc[mt][2 * nt + 1], afrag[mt], bfrag[nt][1], bfrag[nt][3]);
                    }
            }
            __syncthreads();
        }

        const int mrow = lane >> 2;
        const int ncol = (lane & 3) * 2;
#pragma unroll
        for (int mt = 0; mt < 4; mt++) {
            int m0 = bm0 + mh * 128 + wm * 64 + mt * 16 + mrow;
            const float4* h0p = reinterpret_cast<const float4*>(g_H + m0 * 8);
            const float4* h1p = reinterpret_cast<const float4*>(g_H + (m0 + 8) * 8);
            float4 h0a = h0p[0], h0b = h0p[1];
            float4 h1a = h1p[0], h1b = h1p[1];
            float h0r[8] = {h0a.x, h0a.y, h0a.z, h0a.w, h0b.x, h0b.y, h0b.z, h0b.w};
            float h1r[8] = {h1a.x, h1a.y, h1a.z, h1a.w, h1b.x, h1b.y, h1b.z, h1b.w};
#pragma unroll
            for (int nt = 0; nt < 8; nt++) {
                int n0 = bn0 + wn * 64 + nt * 8 + ncol;
                float d00 = 0.f, d01 = 0.f, d10 = 0.f, d11 = 0.f;
#pragma unroll
                for (int r = 0; r < 8; r++) {
                    float l0 = lb[r * N + n0];
                    float l1 = lb[r * N + n0 + 1];
                    d00 += h0r[r] * l0;  d01 += h0r[r] * l1;
                    d10 += h1r[r] * l0;  d11 += h1r[r] * l1;
                }
                __nv_bfloat16 bb0 = __float2bfloat16(bias[n0]);
                __nv_bfloat16 bb1 = __float2bfloat16(bias[n0 + 1]);
                float o00 = __bfloat162float(__hadd(__float2bfloat16(acc[mt][nt][0]), bb0)) + 2.0f * d00;
                float o01 = __bfloat162float(__hadd(__float2bfloat16(acc[mt][nt][1]), bb1)) + 2.0f * d01;
                float o10 = __bfloat162float(__hadd(__float2bfloat16(acc[mt][nt][2]), bb0)) + 2.0f * d10;
                float o11 = __bfloat162float(__hadd(__float2bfloat16(acc[mt][nt][3]), bb1)) + 2.0f * d11;
                *reinterpret_cast<float2*>(out + (size_t)m0 * N + n0)       = make_float2(o00, o01);
                *reinterpret_cast<float2*>(out + (size_t)(m0 + 8) * N + n0) = make_float2(o10, o11);
            }
        }
        __syncthreads();
    }
#endif
}

// ---------------- launch ----------------
extern "C" void kernel_launch(void* const* d_in, const int* in_sizes, int n_in,
                              void* d_out, int out_size) {
    using namespace cfg;
    const float* x = nullptr; const void* q = nullptr; const float* scale = nullptr;
    const float* bias = nullptr; const float* la = nullptr; const float* lb = nullptr;
    for (int i = 0; i < n_in; i++) {
        switch (in_sizes[i]) {
            case 33554432: x = (const float*)d_in[i]; break;        // 8192*4096
            case 16777216: q = d_in[i]; break;                      // 4096*4096
            case 135168:   scale = (const float*)d_in[i]; break;    // 33*4096
            case 4096:     bias = (const float*)d_in[i]; break;
            case 32768:                                             // lora_a then lora_b
                if (!la) la = (const float*)d_in[i];
                else     lb = (const float*)d_in[i];
                break;
            default: break;
        }
    }
    float* out = (float*)d_out;

    k_detect<<<1, 256>>>((const unsigned*)q);
    k_dequant_t<<<dim3(N / 64, K / 64), 256>>>((const int*)q, scale);
    k_lora_conv<<<M / 32, 128>>>(x, la);

    cudaFuncSetAttribute(k_gemm, cudaFuncAttributeMaxDynamicSharedMemorySize, SMEM_TOTAL);
    k_gemm<<<dim3(N / BN, M / BM), 256, SMEM_TOTAL>>>(bias, lb, out);
}